// round 6
// baseline (speedup 1.0000x reference)
#include <cuda_runtime.h>
#include <cuda_bf16.h>
#include <math.h>
#include <stdint.h>

// Problem constants
#define BATCH 2
#define SEQ   2048
#define DIM   4096
#define NHEAD 32
#define HDIM  128
#define MROWS (BATCH * SEQ)   // 4096
#define NELEM (MROWS * DIM)   // 16777216

// fp32 scratch (GEMM outputs, rope inputs)
__device__ float g_q[NELEM];
__device__ float g_k[NELEM];
__device__ float g_v[NELEM];
// pre-split bf16 scratch
__device__ __nv_bfloat16 g_xh[NELEM],  g_xl[NELEM];
__device__ __nv_bfloat16 g_wqh[NELEM], g_wql[NELEM];
__device__ __nv_bfloat16 g_wkh[NELEM], g_wkl[NELEM];
__device__ __nv_bfloat16 g_wvh[NELEM], g_wvl[NELEM];
__device__ __nv_bfloat16 g_woh[NELEM], g_wol[NELEM];
__device__ __nv_bfloat16 g_qh[NELEM],  g_ql[NELEM];
__device__ __nv_bfloat16 g_kh[NELEM],  g_kl[NELEM];
__device__ __nv_bfloat16 g_vh[NELEM],  g_vl[NELEM];
__device__ __nv_bfloat16 g_ah[NELEM],  g_al[NELEM];

// ---------------------------------------------------------------------------
// Helpers
// ---------------------------------------------------------------------------
__device__ __forceinline__ uint32_t smem_u32(const void* p) {
    uint32_t a;
    asm("{ .reg .u64 t; cvta.to.shared.u64 t, %1; cvt.u32.u64 %0, t; }"
        : "=r"(a) : "l"(p));
    return a;
}

__device__ __forceinline__ void cpa16(uint32_t dst, const void* src) {
    asm volatile("cp.async.cg.shared.global [%0], [%1], 16;"
                 :: "r"(dst), "l"(src));
}
#define CP_COMMIT() asm volatile("cp.async.commit_group;" ::: "memory")
#define CP_WAIT(n)  asm volatile("cp.async.wait_group " #n ";" ::: "memory")

__device__ __forceinline__ void ldsm4(uint32_t addr, uint32_t& r0, uint32_t& r1,
                                      uint32_t& r2, uint32_t& r3) {
    asm volatile("ldmatrix.sync.aligned.m8n8.x4.shared.b16 {%0,%1,%2,%3}, [%4];"
                 : "=r"(r0), "=r"(r1), "=r"(r2), "=r"(r3) : "r"(addr));
}
__device__ __forceinline__ void ldsm4t(uint32_t addr, uint32_t& r0, uint32_t& r1,
                                       uint32_t& r2, uint32_t& r3) {
    asm volatile("ldmatrix.sync.aligned.m8n8.x4.trans.shared.b16 {%0,%1,%2,%3}, [%4];"
                 : "=r"(r0), "=r"(r1), "=r"(r2), "=r"(r3) : "r"(addr));
}

__device__ __forceinline__ void mma_bf16(float* c, const uint32_t* a,
                                         const uint32_t* b) {
    asm volatile(
        "mma.sync.aligned.m16n8k16.row.col.f32.bf16.bf16.f32 "
        "{%0,%1,%2,%3}, {%4,%5,%6,%7}, {%8,%9}, {%0,%1,%2,%3};"
        : "+f"(c[0]), "+f"(c[1]), "+f"(c[2]), "+f"(c[3])
        : "r"(a[0]), "r"(a[1]), "r"(a[2]), "r"(a[3]), "r"(b[0]), "r"(b[1]));
}
__device__ __forceinline__ void mma_bf16_2(float* c, const uint32_t* a,
                                           uint32_t b0, uint32_t b1) {
    asm volatile(
        "mma.sync.aligned.m16n8k16.row.col.f32.bf16.bf16.f32 "
        "{%0,%1,%2,%3}, {%4,%5,%6,%7}, {%8,%9}, {%0,%1,%2,%3};"
        : "+f"(c[0]), "+f"(c[1]), "+f"(c[2]), "+f"(c[3])
        : "r"(a[0]), "r"(a[1]), "r"(a[2]), "r"(a[3]), "r"(b0), "r"(b1));
}

__device__ __forceinline__ uint32_t packbf(__nv_bfloat16 a, __nv_bfloat16 b) {
    return ((uint32_t)__bfloat16_as_ushort(b) << 16) | __bfloat16_as_ushort(a);
}
__device__ __forceinline__ void split2(float x, float y, uint32_t& hi, uint32_t& lo) {
    __nv_bfloat16 hx = __float2bfloat16(x);
    __nv_bfloat16 hy = __float2bfloat16(y);
    hi = packbf(hx, hy);
    lo = packbf(__float2bfloat16(x - __bfloat162float(hx)),
                __float2bfloat16(y - __bfloat162float(hy)));
}

// ---------------------------------------------------------------------------
// Split kernel
// ---------------------------------------------------------------------------
__global__ __launch_bounds__(256) void split_kernel(const float* __restrict__ src,
                                                    __nv_bfloat16* __restrict__ dh,
                                                    __nv_bfloat16* __restrict__ dl,
                                                    int n4) {
    int i = blockIdx.x * blockDim.x + threadIdx.x;
    if (i >= n4) return;
    float4 v = ((const float4*)src)[i];
    uint32_t h0, l0, h1, l1;
    split2(v.x, v.y, h0, l0);
    split2(v.z, v.w, h1, l1);
    ((uint2*)dh)[i] = make_uint2(h0, h1);
    ((uint2*)dl)[i] = make_uint2(l0, l1);
}

// ---------------------------------------------------------------------------
// bf16x3-split GEMM v3 (NT): 128x256 tile, BK=32, 8 warps (2x4, 64x64 each),
// 3-stage cp.async pipeline. 192 HMMA/warp/chunk between syncs.
// ---------------------------------------------------------------------------
#define BM 128
#define BN 256
#define BK 32
#define NKC (DIM / BK)   // 128
#define PITCHB 80

#define OFF_AHI 0
#define OFF_ALO 10240
#define OFF_BHI 20480
#define OFF_BLO 40960
#define STAGE_BYTES 61440
#define NSTG 3
#define GEMM_SMEM (NSTG * STAGE_BYTES)   // 184320

__global__ __launch_bounds__(256, 1)
void gemm_bf16x3(const __nv_bfloat16* __restrict__ Ah,
                 const __nv_bfloat16* __restrict__ Al,
                 const __nv_bfloat16* __restrict__ Bh,
                 const __nv_bfloat16* __restrict__ Bl,
                 float* __restrict__ C) {
    extern __shared__ char smem_raw[];
    const uint32_t sbase = smem_u32(smem_raw);
    const int tid  = threadIdx.x;
    const int wid  = tid >> 5;
    const int lane = tid & 31;
    const int wm   = wid >> 2;        // 0..1 (64 m-rows each)
    const int wn   = wid & 3;         // 0..3 (64 n-cols each)
    const int m0   = blockIdx.y * BM;
    const int n0   = blockIdx.x * BN;

    const char* Ahb = (const char*)(Ah + (size_t)m0 * DIM);
    const char* Alb = (const char*)(Al + (size_t)m0 * DIM);
    const char* Bhb = (const char*)(Bh + (size_t)n0 * DIM);
    const char* Blb = (const char*)(Bl + (size_t)n0 * DIM);

    float acc[4][8][4];
#pragma unroll
    for (int i = 0; i < 4; i++)
#pragma unroll
        for (int j = 0; j < 8; j++)
#pragma unroll
            for (int k = 0; k < 4; k++) acc[i][j][k] = 0.0f;

    // cp.async: A 512 segs x2, B 1024 segs x2 = 3072 segs; 12 per thread
#define ISSUE(kc, stg)                                                        \
    {                                                                         \
        uint32_t sb = sbase + (uint32_t)(stg) * STAGE_BYTES;                  \
        size_t gk = (size_t)(kc) * 64;                                        \
        _Pragma("unroll")                                                     \
        for (int u = 0; u < 2; u++) {                                         \
            int seg = tid + u * 256;                                          \
            int row = seg >> 2;                                               \
            int off = (seg & 3) * 16;                                         \
            uint32_t so = (uint32_t)row * PITCHB + off;                       \
            size_t go = (size_t)row * (DIM * 2) + gk + off;                   \
            cpa16(sb + OFF_AHI + so, Ahb + go);                               \
            cpa16(sb + OFF_ALO + so, Alb + go);                               \
        }                                                                     \
        _Pragma("unroll")                                                     \
        for (int u = 0; u < 4; u++) {                                         \
            int seg = tid + u * 256;                                          \
            int row = seg >> 2;                                               \
            int off = (seg & 3) * 16;                                         \
            uint32_t so = (uint32_t)row * PITCHB + off;                       \
            size_t go = (size_t)row * (DIM * 2) + gk + off;                   \
            cpa16(sb + OFF_BHI + so, Bhb + go);                               \
            cpa16(sb + OFF_BLO + so, Blb + go);                               \
        }                                                                     \
        CP_COMMIT();                                                          \
    }

    const uint32_t lm_off = (uint32_t)(lane & 15) * PITCHB + (lane >> 4) * 16;
    const uint32_t aAdr0 = (uint32_t)(wm * 64) * PITCHB + lm_off;
    const uint32_t bAdr0 = (uint32_t)(wn * 64) * PITCHB + lm_off;

    ISSUE(0, 0);
    ISSUE(1, 1);

    for (int kc = 0; kc < NKC; kc++) {
        CP_WAIT(1);
        __syncthreads();
        if (kc + 2 < NKC) { ISSUE(kc + 2, (kc + 2) % 3); }
        else { CP_COMMIT(); }

        const uint32_t stg = sbase + (uint32_t)(kc % 3) * STAGE_BYTES;
        const uint32_t aHi = stg + OFF_AHI + aAdr0;
        const uint32_t aLo = stg + OFF_ALO + aAdr0;
        const uint32_t bHi = stg + OFF_BHI + bAdr0;
        const uint32_t bLo = stg + OFF_BLO + bAdr0;

#pragma unroll
        for (int s = 0; s < 2; s++) {
            uint32_t aF[4][4], bH[8][2], bL[8][2];
#pragma unroll
            for (int mi = 0; mi < 4; mi++)
                ldsm4(aHi + mi * (16 * PITCHB) + s * 32,
                      aF[mi][0], aF[mi][1], aF[mi][2], aF[mi][3]);
#pragma unroll
            for (int nj = 0; nj < 4; nj++) {
                uint32_t r0, r1, r2, r3;
                ldsm4(bHi + nj * (16 * PITCHB) + s * 32, r0, r1, r2, r3);
                bH[nj * 2][0] = r0; bH[nj * 2 + 1][0] = r1;
                bH[nj * 2][1] = r2; bH[nj * 2 + 1][1] = r3;
                ldsm4(bLo + nj * (16 * PITCHB) + s * 32, r0, r1, r2, r3);
                bL[nj * 2][0] = r0; bL[nj * 2 + 1][0] = r1;
                bL[nj * 2][1] = r2; bL[nj * 2 + 1][1] = r3;
            }
            // hh
#pragma unroll
            for (int mi = 0; mi < 4; mi++)
#pragma unroll
                for (int nf = 0; nf < 8; nf++)
                    mma_bf16(acc[mi][nf], aF[mi], bH[nf]);
            // hl
#pragma unroll
            for (int mi = 0; mi < 4; mi++)
#pragma unroll
                for (int nf = 0; nf < 8; nf++)
                    mma_bf16(acc[mi][nf], aF[mi], bL[nf]);
            // lh (reload A-lo over aF)
#pragma unroll
            for (int mi = 0; mi < 4; mi++)
                ldsm4(aLo + mi * (16 * PITCHB) + s * 32,
                      aF[mi][0], aF[mi][1], aF[mi][2], aF[mi][3]);
#pragma unroll
            for (int mi = 0; mi < 4; mi++)
#pragma unroll
                for (int nf = 0; nf < 8; nf++)
                    mma_bf16(acc[mi][nf], aF[mi], bH[nf]);
        }
        __syncthreads();
    }

#pragma unroll
    for (int mi = 0; mi < 4; mi++) {
#pragma unroll
        for (int nf = 0; nf < 8; nf++) {
            int row = m0 + wm * 64 + mi * 16 + (lane >> 2);
            int col = n0 + wn * 64 + nf * 8 + (lane & 3) * 2;
            *(float2*)&C[(size_t)row * DIM + col] =
                make_float2(acc[mi][nf][0], acc[mi][nf][1]);
            *(float2*)&C[(size_t)(row + 8) * DIM + col] =
                make_float2(acc[mi][nf][2], acc[mi][nf][3]);
        }
    }
#undef ISSUE
}

// ---------------------------------------------------------------------------
// RoPE + split
// ---------------------------------------------------------------------------
__global__ __launch_bounds__(256) void rope_split_kernel(
    const float* __restrict__ fcos, const float* __restrict__ fsin) {
    int idx = blockIdx.x * blockDim.x + threadIdx.x;
    int j = idx & 63;
    int h = (idx >> 6) & 31;
    int s = (idx >> 11) & 2047;
    int b = idx >> 22;
    const float scale = 0.08838834764831845f;

    float c = fcos[s * 64 + j];
    float sn = fsin[s * 64 + j];
    size_t base = ((size_t)(b * SEQ + s)) * DIM + h * HDIM + 2 * j;

    float2 q2 = *(const float2*)&g_q[base];
    float2 k2 = *(const float2*)&g_k[base];
    float2 v2 = *(const float2*)&g_v[base];

    float qr = (q2.x * c - q2.y * sn) * scale;
    float qi = (q2.x * sn + q2.y * c) * scale;
    float kr = k2.x * c - k2.y * sn;
    float ki = k2.x * sn + k2.y * c;

    uint32_t hi, lo;
    split2(qr, qi, hi, lo);
    *(uint32_t*)&g_qh[base] = hi;
    *(uint32_t*)&g_ql[base] = lo;
    split2(kr, ki, hi, lo);
    *(uint32_t*)&g_kh[base] = hi;
    *(uint32_t*)&g_kl[base] = lo;
    split2(v2.x, v2.y, hi, lo);
    *(uint32_t*)&g_vh[base] = hi;
    *(uint32_t*)&g_vl[base] = lo;
}

// ---------------------------------------------------------------------------
// Flash attention v2 (unchanged from R5 — at HMMA roofline)
// ---------------------------------------------------------------------------
#define FPITCH 272
#define FQH 0
#define FQL (128 * FPITCH)
#define FSTG0 (2 * 128 * FPITCH)
#define FKH 0
#define FKL (64 * FPITCH)
#define FVH (128 * FPITCH)
#define FVL (192 * FPITCH)
#define FSTAGE (256 * FPITCH)
#define FLASH_SMEM (FSTG0 + 2 * FSTAGE)

__global__ __launch_bounds__(256)
void flash_mma() {
    extern __shared__ char smem_raw[];
    const uint32_t sbase = smem_u32(smem_raw);
    const int tid  = threadIdx.x;
    const int w    = tid >> 5;
    const int lane = tid & 31;
    const int qt = blockIdx.x;
    const int h  = blockIdx.y;
    const int b  = blockIdx.z;
    const int q0 = qt * 128;
    const size_t hoff = (size_t)h * HDIM;

    const char* khb = (const char*)g_kh;
    const char* klb = (const char*)g_kl;
    const char* vhb = (const char*)g_vh;
    const char* vlb = (const char*)g_vl;

    {
        const char* qhb = (const char*)g_qh;
        const char* qlb = (const char*)g_ql;
        for (int i = tid; i < 2048; i += 256) {
            int r = i >> 4, sg = (i & 15) * 16;
            size_t go = ((size_t)(b * SEQ + q0 + r) * DIM + hoff) * 2 + sg;
            uint32_t so = (uint32_t)r * FPITCH + sg;
            *(uint4*)(smem_raw + FQH + so) = *(const uint4*)(qhb + go);
            *(uint4*)(smem_raw + FQL + so) = *(const uint4*)(qlb + go);
        }
    }

#define LOADKV(t, stg)                                                        \
    {                                                                         \
        uint32_t sp = sbase + FSTG0 + (uint32_t)(stg) * FSTAGE;               \
        const int j0 = (t) * 64;                                              \
        _Pragma("unroll")                                                     \
        for (int u = 0; u < 4; u++) {                                         \
            int seg = tid + u * 256;                                          \
            int row = seg >> 4;                                               \
            int off = (seg & 15) * 16;                                        \
            uint32_t so = (uint32_t)row * FPITCH + off;                       \
            size_t go = ((size_t)(b * SEQ + j0 + row) * DIM + hoff) * 2 + off;\
            cpa16(sp + FKH + so, khb + go);                                   \
            cpa16(sp + FKL + so, klb + go);                                   \
            cpa16(sp + FVH + so, vhb + go);                                   \
            cpa16(sp + FVL + so, vlb + go);                                   \
        }                                                                     \
        CP_COMMIT();                                                          \
    }

    LOADKV(0, 0);

    float o[16][4];
#pragma unroll
    for (int nf = 0; nf < 16; nf++)
#pragma unroll
        for (int k = 0; k < 4; k++) o[nf][k] = 0.0f;
    float m0 = -INFINITY, m1 = -INFINITY, l0s = 0.0f, l1s = 0.0f;

    const uint32_t lmA = (uint32_t)(lane & 15) * FPITCH + (lane >> 4) * 16;
    const uint32_t qAdr = sbase + (uint32_t)(w * 16) * FPITCH + lmA;
    const uint32_t lmV = (uint32_t)(((lane >> 3) & 1) * 8 + (lane & 7)) * FPITCH
                         + (lane >> 4) * 16;

    for (int t = 0; t < 32; t++) {
        const int cur = t & 1;
        CP_WAIT(0);
        __syncthreads();
        if (t + 1 < 32) { LOADKV(t + 1, 1 - cur); }

        const uint32_t stg = sbase + FSTG0 + (uint32_t)cur * FSTAGE;

        float sc[8][4];
#pragma unroll
        for (int nf = 0; nf < 8; nf++)
#pragma unroll
            for (int k = 0; k < 4; k++) sc[nf][k] = 0.0f;

#pragma unroll
        for (int ks = 0; ks < 8; ks++) {
            uint32_t qh[4], ql[4];
            ldsm4(qAdr + FQH + ks * 32, qh[0], qh[1], qh[2], qh[3]);
            ldsm4(qAdr + FQL + ks * 32, ql[0], ql[1], ql[2], ql[3]);
#pragma unroll
            for (int nfp = 0; nfp < 4; nfp++) {
                uint32_t kAdr = stg + (uint32_t)(nfp * 16) * FPITCH + lmA + ks * 32;
                uint32_t kh0, kh1, kh2, kh3, kl0, kl1, kl2, kl3;
                ldsm4(kAdr + FKH, kh0, kh1, kh2, kh3);
                ldsm4(kAdr + FKL, kl0, kl1, kl2, kl3);
                mma_bf16_2(sc[nfp * 2],     qh, kh0, kh2);
                mma_bf16_2(sc[nfp * 2 + 1], qh, kh1, kh3);
                mma_bf16_2(sc[nfp * 2],     qh, kl0, kl2);
                mma_bf16_2(sc[nfp * 2 + 1], qh, kl1, kl3);
                mma_bf16_2(sc[nfp * 2],     ql, kh0, kh2);
                mma_bf16_2(sc[nfp * 2 + 1], ql, kh1, kh3);
            }
        }

        float mx0 = -INFINITY, mx1 = -INFINITY;
#pragma unroll
        for (int nf = 0; nf < 8; nf++) {
            mx0 = fmaxf(mx0, fmaxf(sc[nf][0], sc[nf][1]));
            mx1 = fmaxf(mx1, fmaxf(sc[nf][2], sc[nf][3]));
        }
        mx0 = fmaxf(mx0, __shfl_xor_sync(0xffffffffu, mx0, 1));
        mx0 = fmaxf(mx0, __shfl_xor_sync(0xffffffffu, mx0, 2));
        mx1 = fmaxf(mx1, __shfl_xor_sync(0xffffffffu, mx1, 1));
        mx1 = fmaxf(mx1, __shfl_xor_sync(0xffffffffu, mx1, 2));

        float mn0 = fmaxf(m0, mx0), mn1 = fmaxf(m1, mx1);
        float a0 = __expf(m0 - mn0), a1 = __expf(m1 - mn1);
        float rs0 = 0.0f, rs1 = 0.0f;
#pragma unroll
        for (int nf = 0; nf < 8; nf++) {
            sc[nf][0] = __expf(sc[nf][0] - mn0);
            sc[nf][1] = __expf(sc[nf][1] - mn0);
            sc[nf][2] = __expf(sc[nf][2] - mn1);
            sc[nf][3] = __expf(sc[nf][3] - mn1);
            rs0 += sc[nf][0] + sc[nf][1];
            rs1 += sc[nf][2] + sc[nf][3];
        }
        rs0 += __shfl_xor_sync(0xffffffffu, rs0, 1);
        rs0 += __shfl_xor_sync(0xffffffffu, rs0, 2);
        rs1 += __shfl_xor_sync(0xffffffffu, rs1, 1);
        rs1 += __shfl_xor_sync(0xffffffffu, rs1, 2);
        l0s = l0s * a0 + rs0;
        l1s = l1s * a1 + rs1;
        m0 = mn0; m1 = mn1;
#pragma unroll
        for (int nf = 0; nf < 16; nf++) {
            o[nf][0] *= a0; o[nf][1] *= a0;
            o[nf][2] *= a1; o[nf][3] *= a1;
        }

        uint32_t ph[4][4], pl[4][4];
#pragma unroll
        for (int ks = 0; ks < 4; ks++) {
            split2(sc[2 * ks][0],     sc[2 * ks][1],     ph[ks][0], pl[ks][0]);
            split2(sc[2 * ks][2],     sc[2 * ks][3],     ph[ks][1], pl[ks][1]);
            split2(sc[2 * ks + 1][0], sc[2 * ks + 1][1], ph[ks][2], pl[ks][2]);
            split2(sc[2 * ks + 1][2], sc[2 * ks + 1][3], ph[ks][3], pl[ks][3]);
        }

#pragma unroll
        for (int nfp = 0; nfp < 8; nfp++) {
#pragma unroll
            for (int ks = 0; ks < 4; ks++) {
                uint32_t vAdr = stg + (uint32_t)(ks * 16) * FPITCH + lmV + nfp * 32;
                uint32_t vh0, vh1, vh2, vh3, vl0, vl1, vl2, vl3;
                ldsm4t(vAdr + FVH, vh0, vh1, vh2, vh3);
                ldsm4t(vAdr + FVL, vl0, vl1, vl2, vl3);
                mma_bf16_2(o[nfp * 2],     ph[ks], vh0, vh1);
                mma_bf16_2(o[nfp * 2 + 1], ph[ks], vh2, vh3);
                mma_bf16_2(o[nfp * 2],     ph[ks], vl0, vl1);
                mma_bf16_2(o[nfp * 2 + 1], ph[ks], vl2, vl3);
                mma_bf16_2(o[nfp * 2],     pl[ks], vh0, vh1);
                mma_bf16_2(o[nfp * 2 + 1], pl[ks], vh2, vh3);
            }
        }
        __syncthreads();
    }

    const float inv0 = 1.0f / l0s;
    const float inv1 = 1.0f / l1s;
    const int g = lane >> 2;
    const int tq = lane & 3;
    const int row0 = q0 + w * 16 + g;
    size_t base0 = ((size_t)(b * SEQ + row0)) * DIM + hoff + tq * 2;
    size_t base1 = base0 + (size_t)8 * DIM;
#pragma unroll
    for (int nf = 0; nf < 16; nf++) {
        uint32_t hi, lo;
        split2(o[nf][0] * inv0, o[nf][1] * inv0, hi, lo);
        *(uint32_t*)&g_ah[base0 + nf * 8] = hi;
        *(uint32_t*)&g_al[base0 + nf * 8] = lo;
        split2(o[nf][2] * inv1, o[nf][3] * inv1, hi, lo);
        *(uint32_t*)&g_ah[base1 + nf * 8] = hi;
        *(uint32_t*)&g_al[base1 + nf * 8] = lo;
    }
#undef LOADKV
}

// ---------------------------------------------------------------------------
// Launch
// ---------------------------------------------------------------------------
extern "C" void kernel_launch(void* const* d_in, const int* in_sizes, int n_in,
                              void* d_out, int out_size) {
    const float* x    = (const float*)d_in[0];
    const float* wq   = (const float*)d_in[1];
    const float* wk   = (const float*)d_in[2];
    const float* wv   = (const float*)d_in[3];
    const float* wo   = (const float*)d_in[4];
    const float* fcos = (const float*)d_in[5];
    const float* fsin = (const float*)d_in[6];
    float* out = (float*)d_out;

    float *qp, *kp, *vp;
    cudaGetSymbolAddress((void**)&qp, g_q);
    cudaGetSymbolAddress((void**)&kp, g_k);
    cudaGetSymbolAddress((void**)&vp, g_v);

    __nv_bfloat16 *xh, *xl, *wqh, *wql, *wkh, *wkl, *wvh, *wvl, *woh, *wol;
    __nv_bfloat16 *ah, *al;
    cudaGetSymbolAddress((void**)&xh,  g_xh);
    cudaGetSymbolAddress((void**)&xl,  g_xl);
    cudaGetSymbolAddress((void**)&wqh, g_wqh);
    cudaGetSymbolAddress((void**)&wql, g_wql);
    cudaGetSymbolAddress((void**)&wkh, g_wkh);
    cudaGetSymbolAddress((void**)&wkl, g_wkl);
    cudaGetSymbolAddress((void**)&wvh, g_wvh);
    cudaGetSymbolAddress((void**)&wvl, g_wvl);
    cudaGetSymbolAddress((void**)&woh, g_woh);
    cudaGetSymbolAddress((void**)&wol, g_wol);
    cudaGetSymbolAddress((void**)&ah,  g_ah);
    cudaGetSymbolAddress((void**)&al,  g_al);

    cudaFuncSetAttribute(gemm_bf16x3, cudaFuncAttributeMaxDynamicSharedMemorySize,
                         GEMM_SMEM);
    cudaFuncSetAttribute(flash_mma, cudaFuncAttributeMaxDynamicSharedMemorySize,
                         FLASH_SMEM);

    const int n4 = NELEM / 4;
    const int sblk = (n4 + 255) / 256;
    split_kernel<<<sblk, 256>>>(x,  xh,  xl,  n4);
    split_kernel<<<sblk, 256>>>(wq, wqh, wql, n4);
    split_kernel<<<sblk, 256>>>(wk, wkh, wkl, n4);
    split_kernel<<<sblk, 256>>>(wv, wvh, wvl, n4);
    split_kernel<<<sblk, 256>>>(wo, woh, wol, n4);

    dim3 ggrid(DIM / BN, MROWS / BM);   // (16, 32)
    gemm_bf16x3<<<ggrid, 256, GEMM_SMEM>>>(xh, xl, wqh, wql, qp);
    gemm_bf16x3<<<ggrid, 256, GEMM_SMEM>>>(xh, xl, wkh, wkl, kp);
    gemm_bf16x3<<<ggrid, 256, GEMM_SMEM>>>(xh, xl, wvh, wvl, vp);

    rope_split_kernel<<<(BATCH * SEQ * NHEAD * 64) / 256, 256>>>(fcos, fsin);

    flash_mma<<<dim3(SEQ / 128, NHEAD, BATCH), 256, FLASH_SMEM>>>();

    gemm_bf16x3<<<ggrid, 256, GEMM_SMEM>>>(ah, al, woh, wol, out);
}